// round 6
// baseline (speedup 1.0000x reference)
#include <cuda_runtime.h>
#include <math.h>

#define D        32
#define SPLITS   11
#define TT       64
#define BLK      128
#define QT       2
#define QB       (BLK*QT)      // 256 queries per block
#define M_MAX    16384
#define N_MAX    8192
#define EPSV     1e-8f
#define BWB      64

// ---------------- device scratch ----------------
__device__ float        g_cl;                       // c * log2(e)
__device__ float4       g_terr[N_MAX];              // (t2, 1, r, 1)
__device__ double       g_bws [BWB * D];
__device__ double       g_bws2[BWB * D];
__device__ float        g_pnum[SPLITS][M_MAX];
__device__ float        g_pden[SPLITS][M_MAX];
__device__ float        g_rx[M_MAX];
__device__ unsigned int g_rmin, g_rmax, g_smin, g_smax;

// ---------------- helpers ----------------
__device__ __forceinline__ unsigned long long pack2(float lo, float hi) {
    unsigned long long r;
    asm("mov.b64 %0, {%1, %2};" : "=l"(r) : "f"(lo), "f"(hi));
    return r;
}
__device__ __forceinline__ unsigned long long dup2(float v) {
    unsigned long long r;
    asm("mov.b64 %0, {%1, %1};" : "=l"(r) : "f"(v));
    return r;
}
__device__ __forceinline__ unsigned long long fma2(unsigned long long a,
                                                   unsigned long long b,
                                                   unsigned long long c) {
    unsigned long long d;
    asm("fma.rn.f32x2 %0, %1, %2, %3;" : "=l"(d) : "l"(a), "l"(b), "l"(c));
    return d;
}
__device__ __forceinline__ unsigned long long add2(unsigned long long a,
                                                   unsigned long long b) {
    unsigned long long d;
    asm("add.rn.f32x2 %0, %1, %2;" : "=l"(d) : "l"(a), "l"(b));
    return d;
}
__device__ __forceinline__ float2 unpack2(unsigned long long p) {
    float2 f;
    asm("mov.b64 {%0, %1}, %2;" : "=f"(f.x), "=f"(f.y) : "l"(p));
    return f;
}
__device__ __forceinline__ float ex2f(float a) {
    float r;
    asm("ex2.approx.f32 %0, %1;" : "=f"(r) : "f"(a));
    return r;
}
__device__ __forceinline__ void cp16(unsigned int dst_smem, const void* src) {
    asm volatile("cp.async.ca.shared.global [%0], [%1], 16;"
                 :: "r"(dst_smem), "l"(src));
}
__device__ __forceinline__ unsigned int fenc(float f) {
    unsigned int u = __float_as_uint(f);
    return (u & 0x80000000u) ? ~u : (u | 0x80000000u);
}
__device__ __forceinline__ float fdec(unsigned int u) {
    u = (u & 0x80000000u) ? (u & 0x7fffffffu) : ~u;
    return __uint_as_float(u);
}
__device__ __forceinline__ float warp_min(float v) {
    #pragma unroll
    for (int o = 16; o; o >>= 1) v = fminf(v, __shfl_xor_sync(0xffffffffu, v, o));
    return v;
}
__device__ __forceinline__ float warp_max(float v) {
    #pragma unroll
    for (int o = 16; o; o >>= 1) v = fmaxf(v, __shfl_xor_sync(0xffffffffu, v, o));
    return v;
}

// ---------------- bandwidth phase 1 ----------------
__global__ void k_bw1(const float* __restrict__ tx) {
    __shared__ double sds [8][8][4];
    __shared__ double sds2[8][8][4];
    const int tid = threadIdx.x;
    const int b   = blockIdx.x;
    const float4* tx4 = (const float4*)tx;

    double s[4] = {0, 0, 0, 0}, s2[4] = {0, 0, 0, 0};
    #pragma unroll
    for (int it = 0; it < 4; it++) {
        float4 v = tx4[(size_t)(b * 128 + it * 32) * 8 + tid];
        double vx = v.x, vy = v.y, vz = v.z, vw = v.w;
        s[0] += vx; s2[0] += vx * vx;
        s[1] += vy; s2[1] += vy * vy;
        s[2] += vz; s2[2] += vz * vz;
        s[3] += vw; s2[3] += vw * vw;
    }
    #pragma unroll
    for (int o = 8; o <= 16; o <<= 1) {
        #pragma unroll
        for (int k = 0; k < 4; k++) {
            s [k] += __shfl_xor_sync(0xffffffffu, s [k], o);
            s2[k] += __shfl_xor_sync(0xffffffffu, s2[k], o);
        }
    }
    int w = tid >> 5, l = tid & 31;
    if (l < 8) {
        #pragma unroll
        for (int k = 0; k < 4; k++) { sds[w][l][k] = s[k]; sds2[w][l][k] = s2[k]; }
    }
    __syncthreads();
    if (tid < 8) {
        #pragma unroll
        for (int k = 0; k < 4; k++) {
            double a = 0, a2 = 0;
            #pragma unroll
            for (int ww = 0; ww < 8; ww++) { a += sds[ww][tid][k]; a2 += sds2[ww][tid][k]; }
            g_bws [b * D + tid * 4 + k] = a;
            g_bws2[b * D + tid * 4 + k] = a2;
        }
    }
}

// ---------------- bandwidth phase 2 ----------------
__global__ void k_bw2(int n) {
    int d = threadIdx.x;
    double s = 0, s2 = 0;
    for (int b = 0; b < BWB; b++) { s += g_bws[b * D + d]; s2 += g_bws2[b * D + d]; }
    double mean = s / (double)n;
    double var  = (s2 - (double)n * mean * mean) / (double)(n - 1);
    double sd   = sqrt(var > 0.0 ? var : 0.0);
    #pragma unroll
    for (int o = 16; o; o >>= 1) sd += __shfl_xor_sync(0xffffffffu, sd, o);
    if (d == 0) {
        double ms = sd / (double)D;
        double bw = ms * exp(-log((double)n) / (double)(D + 4));
        double c  = 1.0 / (2.0 * bw * bw);
        g_cl = (float)(c * 1.4426950408889634);
        g_rmin = 0xFFFFFFFFu; g_rmax = 0u;
        g_smin = 0xFFFFFFFFu; g_smax = 0u;
    }
}

// ---------------- train extension vectors (independent of bandwidth) ---------
__global__ void k_t2(const float* __restrict__ tx, const float* __restrict__ tr, int n) {
    int j = blockIdx.x * blockDim.x + threadIdx.x;
    if (j >= n) return;
    const float4* r = (const float4*)(tx + (size_t)j * D);
    float s = 0.f;
    #pragma unroll
    for (int k = 0; k < D / 4; k++) {
        float4 v = r[k];
        s = fmaf(v.x, v.x, s); s = fmaf(v.y, v.y, s);
        s = fmaf(v.z, v.z, s); s = fmaf(v.w, v.w, s);
    }
    g_terr[j] = make_float4(s, 1.0f, tr[j], 1.0f);   // raw t2; -cl folded query-side
}

// ---------------- pairwise KDE mainloop ----------------
// 2 queries/thread (q, q+BLK), 128 thr, occ 5 (20 warps/SM). Double-buffered cp.async.
__global__ void __launch_bounds__(BLK, 5)
k_main(const float* __restrict__ x, const float* __restrict__ tx, int m, int n) {
    __shared__ float4 sh_c[2][TT * 8];
    __shared__ float4 sh_e[2][TT];

    const float cl = g_cl;
    const float K2 = cl + cl;
    const int tid = threadIdx.x;
    const int q0  = blockIdx.x * QB + tid;
    const int q1  = q0 + BLK;

    unsigned long long qr0[D / 2 + 1], qr1[D / 2 + 1];
    {
        const float4* p0 = (const float4*)(x + (size_t)q0 * D);
        const float4* p1 = (const float4*)(x + (size_t)q1 * D);
        float q2_0 = 0.f, q2_1 = 0.f;
        #pragma unroll
        for (int k = 0; k < D / 4; k++) {
            float4 a = p0[k], b = p1[k];
            q2_0 = fmaf(a.x, a.x, q2_0); q2_0 = fmaf(a.y, a.y, q2_0);
            q2_0 = fmaf(a.z, a.z, q2_0); q2_0 = fmaf(a.w, a.w, q2_0);
            q2_1 = fmaf(b.x, b.x, q2_1); q2_1 = fmaf(b.y, b.y, q2_1);
            q2_1 = fmaf(b.z, b.z, q2_1); q2_1 = fmaf(b.w, b.w, q2_1);
            qr0[2 * k]     = pack2(a.x * K2, a.y * K2);
            qr0[2 * k + 1] = pack2(a.z * K2, a.w * K2);
            qr1[2 * k]     = pack2(b.x * K2, b.y * K2);
            qr1[2 * k + 1] = pack2(b.z * K2, b.w * K2);
        }
        qr0[D / 2] = pack2(-cl, -cl * q2_0);   // fma with (t2, 1) adds (-cl*t2, -cl*q2)
        qr1[D / 2] = pack2(-cl, -cl * q2_1);
    }

    unsigned long long nd0 = 0ull, nd1 = 0ull;

    const int NT = n / TT;
    const int tb_lo = (blockIdx.y * NT) / SPLITS;
    const int tb_hi = ((blockIdx.y + 1) * NT) / SPLITS;

    unsigned int sc0 = (unsigned int)__cvta_generic_to_shared(&sh_c[0][0]);
    unsigned int sc1 = (unsigned int)__cvta_generic_to_shared(&sh_c[1][0]);
    unsigned int se0 = (unsigned int)__cvta_generic_to_shared(&sh_e[0][0]);
    unsigned int se1 = (unsigned int)__cvta_generic_to_shared(&sh_e[1][0]);

    auto issue = [&](int tb, int buf) {
        const float4* src = ((const float4*)tx) + (size_t)tb * TT * 8;
        unsigned int dc = buf ? sc1 : sc0;
        unsigned int de = buf ? se1 : se0;
        #pragma unroll
        for (int i = 0; i < 4; i++)
            cp16(dc + (tid + i * BLK) * 16, src + tid + i * BLK);
        if (tid < TT) cp16(de + tid * 16, g_terr + (size_t)tb * TT + tid);
        asm volatile("cp.async.commit_group;");
    };

    issue(tb_lo, 0);
    int buf = 0;
    for (int tb = tb_lo; tb < tb_hi; tb++) {
        if (tb + 1 < tb_hi) {
            issue(tb + 1, buf ^ 1);
            asm volatile("cp.async.wait_group 1;");
        } else {
            asm volatile("cp.async.wait_group 0;");
        }
        __syncthreads();

        const ulonglong2* cbase = (const ulonglong2*)(buf ? &sh_c[1][0] : &sh_c[0][0]);
        const ulonglong2* ebase = (const ulonglong2*)(buf ? &sh_e[1][0] : &sh_e[0][0]);

        #pragma unroll 2
        for (int t = 0; t < TT; t++) {
            const ulonglong2* tv = cbase + t * 8;
            unsigned long long a0x = 0ull, a0y = 0ull, a1x = 0ull, a1y = 0ull;
            #pragma unroll
            for (int k = 0; k < 8; k++) {
                ulonglong2 w = tv[k];
                a0x = fma2(qr0[2 * k],     w.x, a0x);
                a0y = fma2(qr0[2 * k + 1], w.y, a0y);
                a1x = fma2(qr1[2 * k],     w.x, a1x);
                a1y = fma2(qr1[2 * k + 1], w.y, a1y);
            }
            ulonglong2 e = ebase[t];
            a0x = fma2(qr0[D / 2], e.x, a0x);
            a1x = fma2(qr1[D / 2], e.x, a1x);
            unsigned long long s0 = add2(a0x, a0y);
            unsigned long long s1 = add2(a1x, a1y);
            float2 f0 = unpack2(s0), f1 = unpack2(s1);
            float w0 = ex2f(f0.x + f0.y);
            float w1 = ex2f(f1.x + f1.y);
            nd0 = fma2(dup2(w0), e.y, nd0);
            nd1 = fma2(dup2(w1), e.y, nd1);
        }
        __syncthreads();
        buf ^= 1;
    }

    float2 r0 = unpack2(nd0), r1 = unpack2(nd1);
    g_pnum[blockIdx.y][q0] = r0.x;
    g_pden[blockIdx.y][q0] = r0.y;
    g_pnum[blockIdx.y][q1] = r1.x;
    g_pden[blockIdx.y][q1] = r1.y;
}

// ---------------- reduce splits -> rx, global min/max ----------------
__global__ void k_reduce(const float* __restrict__ sig, int m) {
    __shared__ float s_rmin[8], s_rmax[8], s_smin[8], s_smax[8];
    int q = blockIdx.x * blockDim.x + threadIdx.x;
    float rx = 3.4e38f, rxmx = -3.4e38f, sg = 3.4e38f, sgmx = -3.4e38f;
    if (q < m) {
        float num = 0.f, den = 0.f;
        #pragma unroll
        for (int s = 0; s < SPLITS; s++) { num += g_pnum[s][q]; den += g_pden[s][q]; }
        float r = num / (den + EPSV);
        g_rx[q] = r;
        rx = r; rxmx = r;
        float sv = sig[q];
        sg = sv; sgmx = sv;
    }
    float wmin_r = warp_min(rx),  wmax_r = warp_max(rxmx);
    float wmin_s = warp_min(sg),  wmax_s = warp_max(sgmx);
    int w = threadIdx.x >> 5, l = threadIdx.x & 31;
    int nw = blockDim.x >> 5;
    if (l == 0) { s_rmin[w] = wmin_r; s_rmax[w] = wmax_r; s_smin[w] = wmin_s; s_smax[w] = wmax_s; }
    __syncthreads();
    if (threadIdx.x == 0) {
        float bmin_r = s_rmin[0], bmax_r = s_rmax[0], bmin_s = s_smin[0], bmax_s = s_smax[0];
        for (int i = 1; i < nw; i++) {
            bmin_r = fminf(bmin_r, s_rmin[i]); bmax_r = fmaxf(bmax_r, s_rmax[i]);
            bmin_s = fminf(bmin_s, s_smin[i]); bmax_s = fmaxf(bmax_s, s_smax[i]);
        }
        atomicMin(&g_rmin, fenc(bmin_r)); atomicMax(&g_rmax, fenc(bmax_r));
        atomicMin(&g_smin, fenc(bmin_s)); atomicMax(&g_smax, fenc(bmax_s));
    }
}

// ---------------- final normalize + combine ----------------
__global__ void k_final(const float* __restrict__ sig, float* __restrict__ out, int m) {
    int q = blockIdx.x * blockDim.x + threadIdx.x;
    if (q >= m) return;
    float rmin = fdec(g_rmin), rmax = fdec(g_rmax);
    float smin = fdec(g_smin), smax = fdec(g_smax);
    float t1 = 0.5f * (g_rx[q] - rmin) / (rmax - rmin + EPSV);
    float t2 = 0.5f * (sig[q]  - smin) / (smax - smin + EPSV);
    out[q] = t1 + t2;
}

// ---------------- launch ----------------
extern "C" void kernel_launch(void* const* d_in, const int* in_sizes, int n_in,
                              void* d_out, int out_size) {
    const float* x   = (const float*)d_in[0];   // [m, 32]
    const float* tx  = (const float*)d_in[1];   // [n, 32]
    const float* tr  = (const float*)d_in[2];   // [n]
    const float* sig = (const float*)d_in[3];   // [m]
    int m = in_sizes[0] / D;   // 16384
    int n = in_sizes[1] / D;   // 8192

    k_t2<<<(n + 255) / 256, 256>>>(tx, tr, n);
    k_bw1<<<BWB, 256>>>(tx);
    k_bw2<<<1, 32>>>(n);
    dim3 grid(m / QB, SPLITS);
    k_main<<<grid, BLK>>>(x, tx, m, n);
    k_reduce<<<(m + 255) / 256, 256>>>(sig, m);
    k_final<<<(m + 255) / 256, 256>>>(sig, (float*)d_out, m);
}

// round 8
// speedup vs baseline: 1.7843x; 1.7843x over previous
#include <cuda_runtime.h>
#include <cuda_bf16.h>
#include <math.h>

#define D        32
#define TSPLIT   8
#define NTT      64            // train per tile
#define MQ       128           // queries per CTA
#define M_MAX    16384
#define N_MAX    8192
#define EPSV     1e-8f
#define BWB      64

// smem: pitch-80 rows. Tile buf: Bhi[0,5120) Blo[5120,10240) ext[10240,10752)
#define PITCH    80
#define BUFSZ    10752
#define SMEMSZ   (2*BUFSZ)     // 21504; A staging (20480) aliases both bufs pre-loop

__device__ float         g_cl;
__device__ __nv_bfloat16 g_Ah[M_MAX * D];   // K2-scaled query hi
__device__ __nv_bfloat16 g_Al[M_MAX * D];   // K2-scaled query lo
__device__ __nv_bfloat16 g_Bh[N_MAX * D];   // train hi
__device__ __nv_bfloat16 g_Bl[N_MAX * D];   // train lo
__device__ float4        g_ext4[N_MAX / 2]; // {ct2_even, ct2_odd, r_even, r_odd}
__device__ float         g_qe[M_MAX];       // -cl*q^2
__device__ double        g_bws [BWB * D];
__device__ double        g_bws2[BWB * D];
__device__ float         g_pnum[TSPLIT][M_MAX];
__device__ float         g_pden[TSPLIT][M_MAX];
__device__ float         g_rx[M_MAX];
__device__ unsigned int  g_rmin, g_rmax, g_smin, g_smax;

// ---------------- helpers ----------------
__device__ __forceinline__ unsigned long long pack2(float lo, float hi) {
    unsigned long long r; asm("mov.b64 %0, {%1, %2};" : "=l"(r) : "f"(lo), "f"(hi)); return r;
}
__device__ __forceinline__ unsigned long long dup2(float v) {
    unsigned long long r; asm("mov.b64 %0, {%1, %1};" : "=l"(r) : "f"(v)); return r;
}
__device__ __forceinline__ unsigned long long add2(unsigned long long a, unsigned long long b) {
    unsigned long long d; asm("add.rn.f32x2 %0, %1, %2;" : "=l"(d) : "l"(a), "l"(b)); return d;
}
__device__ __forceinline__ float2 unpack2(unsigned long long p) {
    float2 f; asm("mov.b64 {%0, %1}, %2;" : "=f"(f.x), "=f"(f.y) : "l"(p)); return f;
}
__device__ __forceinline__ float ex2f(float a) {
    float r; asm("ex2.approx.f32 %0, %1;" : "=f"(r) : "f"(a)); return r;
}
__device__ __forceinline__ void cp16(unsigned dst, const void* src) {
    asm volatile("cp.async.ca.shared.global [%0], [%1], 16;" :: "r"(dst), "l"(src));
}
__device__ __forceinline__ unsigned fenc(float f) {
    unsigned u = __float_as_uint(f); return (u & 0x80000000u) ? ~u : (u | 0x80000000u);
}
__device__ __forceinline__ float fdec(unsigned u) {
    u = (u & 0x80000000u) ? (u & 0x7fffffffu) : ~u; return __uint_as_float(u);
}
__device__ __forceinline__ float warp_min(float v) {
    #pragma unroll
    for (int o = 16; o; o >>= 1) v = fminf(v, __shfl_xor_sync(~0u, v, o));
    return v;
}
__device__ __forceinline__ float warp_max(float v) {
    #pragma unroll
    for (int o = 16; o; o >>= 1) v = fmaxf(v, __shfl_xor_sync(~0u, v, o));
    return v;
}
__device__ __forceinline__ void ldmx4(unsigned* r, unsigned addr) {
    asm volatile("ldmatrix.sync.aligned.m8n8.x4.shared.b16 {%0,%1,%2,%3}, [%4];"
                 : "=r"(r[0]), "=r"(r[1]), "=r"(r[2]), "=r"(r[3]) : "r"(addr));
}
__device__ __forceinline__ void mma16816(float* c, const unsigned* a, unsigned b0, unsigned b1) {
    asm volatile("mma.sync.aligned.m16n8k16.row.col.f32.bf16.bf16.f32 "
                 "{%0,%1,%2,%3}, {%4,%5,%6,%7}, {%8,%9}, {%0,%1,%2,%3};"
                 : "+f"(c[0]), "+f"(c[1]), "+f"(c[2]), "+f"(c[3])
                 : "r"(a[0]), "r"(a[1]), "r"(a[2]), "r"(a[3]), "r"(b0), "r"(b1));
}

// ---------------- bandwidth ----------------
__global__ void k_bw1(const float* __restrict__ tx) {
    __shared__ double sds[8][8][4], sds2[8][8][4];
    const int tid = threadIdx.x, b = blockIdx.x;
    const float4* tx4 = (const float4*)tx;
    double s[4] = {0,0,0,0}, s2[4] = {0,0,0,0};
    #pragma unroll
    for (int it = 0; it < 4; it++) {
        float4 v = tx4[(size_t)(b * 128 + it * 32) * 8 + tid];
        double vx = v.x, vy = v.y, vz = v.z, vw = v.w;
        s[0] += vx; s2[0] += vx*vx; s[1] += vy; s2[1] += vy*vy;
        s[2] += vz; s2[2] += vz*vz; s[3] += vw; s2[3] += vw*vw;
    }
    #pragma unroll
    for (int o = 8; o <= 16; o <<= 1)
        #pragma unroll
        for (int k = 0; k < 4; k++) {
            s[k]  += __shfl_xor_sync(~0u, s[k],  o);
            s2[k] += __shfl_xor_sync(~0u, s2[k], o);
        }
    int w = tid >> 5, l = tid & 31;
    if (l < 8)
        #pragma unroll
        for (int k = 0; k < 4; k++) { sds[w][l][k] = s[k]; sds2[w][l][k] = s2[k]; }
    __syncthreads();
    if (tid < 8)
        #pragma unroll
        for (int k = 0; k < 4; k++) {
            double a = 0, a2 = 0;
            #pragma unroll
            for (int ww = 0; ww < 8; ww++) { a += sds[ww][tid][k]; a2 += sds2[ww][tid][k]; }
            g_bws[b * D + tid * 4 + k] = a; g_bws2[b * D + tid * 4 + k] = a2;
        }
}
__global__ void k_bw2(int n) {
    int d = threadIdx.x;
    double s = 0, s2 = 0;
    for (int b = 0; b < BWB; b++) { s += g_bws[b * D + d]; s2 += g_bws2[b * D + d]; }
    double mean = s / n, var = (s2 - n * mean * mean) / (n - 1);
    double sd = sqrt(var > 0.0 ? var : 0.0);
    #pragma unroll
    for (int o = 16; o; o >>= 1) sd += __shfl_xor_sync(~0u, sd, o);
    if (d == 0) {
        double bw = (sd / D) * exp(-log((double)n) / (D + 4));
        g_cl = (float)(1.0 / (2.0 * bw * bw) * 1.4426950408889634);
        g_rmin = ~0u; g_rmax = 0u; g_smin = ~0u; g_smax = 0u;
    }
}

// ---------------- prep: bf16 hi/lo split ----------------
__global__ void k_qprep(const float* __restrict__ x, int m) {
    int q = blockIdx.x * 256 + threadIdx.x;
    if (q >= m) return;
    const float* p = x + (size_t)q * D;
    float cl = g_cl, K2 = cl + cl, q2 = 0.f;
    __nv_bfloat16* dh = g_Ah + (size_t)q * D;
    __nv_bfloat16* dl = g_Al + (size_t)q * D;
    #pragma unroll
    for (int k = 0; k < D; k++) {
        float v = p[k];
        q2 = fmaf(v, v, q2);
        float sv = v * K2;
        __nv_bfloat16 h = __float2bfloat16_rn(sv);
        dh[k] = h;
        dl[k] = __float2bfloat16_rn(sv - __bfloat162float(h));
    }
    g_qe[q] = -cl * q2;
}
__global__ void k_tprep(const float* __restrict__ tx, const float* __restrict__ tr, int n) {
    int j = blockIdx.x * 256 + threadIdx.x;
    if (j >= n) return;
    const float* p = tx + (size_t)j * D;
    float t2 = 0.f;
    __nv_bfloat16* dh = g_Bh + (size_t)j * D;
    __nv_bfloat16* dl = g_Bl + (size_t)j * D;
    #pragma unroll
    for (int k = 0; k < D; k++) {
        float v = p[k];
        t2 = fmaf(v, v, t2);
        __nv_bfloat16 h = __float2bfloat16_rn(v);
        dh[k] = h;
        dl[k] = __float2bfloat16_rn(v - __bfloat162float(h));
    }
    float* e = (float*)&g_ext4[j >> 1];
    if (j & 1) { e[1] = -g_cl * t2; e[3] = tr[j]; }
    else       { e[0] = -g_cl * t2; e[2] = tr[j]; }
}

// ---------------- HMMA KDE mainloop ----------------
__device__ __forceinline__ void load_tile(unsigned sb, int g, int b, int tid) {
    unsigned base = sb + b * BUFSZ;
    const __nv_bfloat16* sh = g_Bh + (size_t)g * NTT * D;
    const __nv_bfloat16* sl = g_Bl + (size_t)g * NTT * D;
    int row = tid >> 2, c = tid & 3;
    cp16(base + row * PITCH + c * 16, sh + row * D + c * 8);
    cp16(base + 5120 + row * PITCH + c * 16, sl + row * D + c * 8);
    if (tid < 32) cp16(base + 10240 + tid * 16, g_ext4 + (size_t)g * 32 + tid);
    asm volatile("cp.async.commit_group;" ::: "memory");
}

__global__ void __launch_bounds__(256, 3)
k_main_mma(int n) {
    __shared__ __align__(16) char smem[SMEMSZ];
    unsigned sb = (unsigned)__cvta_generic_to_shared(smem);
    const int tid = threadIdx.x, w = tid >> 5, lane = tid & 31;
    const int qblk = blockIdx.x, split = blockIdx.y;
    const int NT = (n / NTT) / TSPLIT;
    const int t0 = split * NT;

    // ---- stage A (hi at sb, lo at sb+10240), extract frags, then reuse smem ----
    #pragma unroll
    for (int i = 0; i < 2; i++) {
        int idx = tid + i * 256, row = idx >> 2, c = idx & 3;
        cp16(sb + row * PITCH + c * 16, g_Ah + (size_t)(qblk * MQ + row) * D + c * 8);
        cp16(sb + 10240 + row * PITCH + c * 16, g_Al + (size_t)(qblk * MQ + row) * D + c * 8);
    }
    asm volatile("cp.async.commit_group;" ::: "memory");
    asm volatile("cp.async.wait_group 0;" ::: "memory");
    __syncthreads();

    unsigned ah[2][4], al[2][4];
    {
        unsigned rowsel = lane & 15, colb = (lane >> 4) * 16;
        unsigned abase = sb + (w * 16 + rowsel) * PITCH + colb;
        ldmx4(ah[0], abase);
        ldmx4(ah[1], abase + 32);
        ldmx4(al[0], abase + 10240);
        ldmx4(al[1], abase + 10240 + 32);
    }
    const int qg = lane >> 2;
    const unsigned long long cq2a = dup2(g_qe[qblk * MQ + w * 16 + qg]);
    const unsigned long long cq2b = dup2(g_qe[qblk * MQ + w * 16 + qg + 8]);
    __syncthreads();                               // done with staged A

    load_tile(sb, t0, 0, tid);

    float num_a = 0.f, den_a = 0.f, num_b = 0.f, den_b = 0.f;

    // B-frag ldmatrix address pieces (pitch-80 rows → conflict-free)
    const unsigned browAdd = (lane >> 4) * 8 + (lane & 7);
    const unsigned bcolb   = ((lane >> 3) & 1) * 16;

    for (int i = 0; i < NT; i++) {
        const int buf = i & 1;
        if (i + 1 < NT) {
            load_tile(sb, t0 + i + 1, buf ^ 1, tid);
            asm volatile("cp.async.wait_group 1;" ::: "memory");
        } else {
            asm volatile("cp.async.wait_group 0;" ::: "memory");
        }
        __syncthreads();

        const unsigned bbase = sb + buf * BUFSZ;
        float c[8][4];
        #pragma unroll
        for (int s = 0; s < 8; s++)
            #pragma unroll
            for (int k = 0; k < 4; k++) c[s][k] = 0.f;

        #pragma unroll
        for (int np = 0; np < 4; np++) {
            const unsigned rb = bbase + (np * 16 + browAdd) * PITCH + bcolb;
            #pragma unroll
            for (int ks = 0; ks < 2; ks++) {
                unsigned bh[4], bl[4];
                ldmx4(bh, rb + ks * 32);
                ldmx4(bl, rb + 5120 + ks * 32);
                #pragma unroll
                for (int ns = 0; ns < 2; ns++) {
                    float* cc = c[np * 2 + ns];
                    mma16816(cc, ah[ks], bh[ns * 2], bh[ns * 2 + 1]);
                    mma16816(cc, al[ks], bh[ns * 2], bh[ns * 2 + 1]);
                    mma16816(cc, ah[ks], bl[ns * 2], bl[ns * 2 + 1]);
                    mma16816(cc, al[ks], bl[ns * 2], bl[ns * 2 + 1]);
                }
            }
        }

        // epilogue: arg = dot + (-cl t2) + (-cl q2); w = ex2(arg); nd += w*(r,1)
        const float4* ext = (const float4*)(smem + buf * BUFSZ + 10240);
        #pragma unroll
        for (int s = 0; s < 8; s++) {
            float4 e = ext[s * 4 + (lane & 3)];    // {ct2_0, ct2_1, r_0, r_1}
            unsigned long long ct = pack2(e.x, e.y);
            unsigned long long pa = add2(add2(pack2(c[s][0], c[s][1]), ct), cq2a);
            unsigned long long pb = add2(add2(pack2(c[s][2], c[s][3]), ct), cq2b);
            float2 fa = unpack2(pa), fb = unpack2(pb);
            float w0 = ex2f(fa.x), w1 = ex2f(fa.y);
            float w2 = ex2f(fb.x), w3 = ex2f(fb.y);
            num_a = fmaf(w0, e.z, num_a); num_a = fmaf(w1, e.w, num_a);
            den_a += w0 + w1;
            num_b = fmaf(w2, e.z, num_b); num_b = fmaf(w3, e.w, num_b);
            den_b += w2 + w3;
        }
        __syncthreads();                           // all warps done with buf
    }

    // quad reduction (lanes sharing a row differ only in lane&3)
    #pragma unroll
    for (int o = 1; o <= 2; o <<= 1) {
        num_a += __shfl_xor_sync(~0u, num_a, o);
        den_a += __shfl_xor_sync(~0u, den_a, o);
        num_b += __shfl_xor_sync(~0u, num_b, o);
        den_b += __shfl_xor_sync(~0u, den_b, o);
    }
    if ((lane & 3) == 0) {
        int q = qblk * MQ + w * 16 + qg;
        g_pnum[split][q] = num_a;     g_pden[split][q] = den_a;
        g_pnum[split][q + 8] = num_b; g_pden[split][q + 8] = den_b;
    }
}

// ---------------- reduce + final ----------------
__global__ void k_reduce(const float* __restrict__ sig, int m) {
    __shared__ float s_rmin[8], s_rmax[8], s_smin[8], s_smax[8];
    int q = blockIdx.x * blockDim.x + threadIdx.x;
    float rx = 3.4e38f, rxmx = -3.4e38f, sg = 3.4e38f, sgmx = -3.4e38f;
    if (q < m) {
        float num = 0.f, den = 0.f;
        #pragma unroll
        for (int s = 0; s < TSPLIT; s++) { num += g_pnum[s][q]; den += g_pden[s][q]; }
        float r = num / (den + EPSV);
        g_rx[q] = r; rx = r; rxmx = r;
        float sv = sig[q]; sg = sv; sgmx = sv;
    }
    float wr0 = warp_min(rx), wr1 = warp_max(rxmx), ws0 = warp_min(sg), ws1 = warp_max(sgmx);
    int w = threadIdx.x >> 5, l = threadIdx.x & 31, nw = blockDim.x >> 5;
    if (l == 0) { s_rmin[w] = wr0; s_rmax[w] = wr1; s_smin[w] = ws0; s_smax[w] = ws1; }
    __syncthreads();
    if (threadIdx.x == 0) {
        float a = s_rmin[0], b = s_rmax[0], cc = s_smin[0], d = s_smax[0];
        for (int i = 1; i < nw; i++) {
            a = fminf(a, s_rmin[i]); b = fmaxf(b, s_rmax[i]);
            cc = fminf(cc, s_smin[i]); d = fmaxf(d, s_smax[i]);
        }
        atomicMin(&g_rmin, fenc(a)); atomicMax(&g_rmax, fenc(b));
        atomicMin(&g_smin, fenc(cc)); atomicMax(&g_smax, fenc(d));
    }
}
__global__ void k_final(const float* __restrict__ sig, float* __restrict__ out, int m) {
    int q = blockIdx.x * blockDim.x + threadIdx.x;
    if (q >= m) return;
    float t1 = 0.5f * (g_rx[q] - fdec(g_rmin)) / (fdec(g_rmax) - fdec(g_rmin) + EPSV);
    float t2 = 0.5f * (sig[q]  - fdec(g_smin)) / (fdec(g_smax) - fdec(g_smin) + EPSV);
    out[q] = t1 + t2;
}

// ---------------- launch ----------------
extern "C" void kernel_launch(void* const* d_in, const int* in_sizes, int n_in,
                              void* d_out, int out_size) {
    const float* x   = (const float*)d_in[0];
    const float* tx  = (const float*)d_in[1];
    const float* tr  = (const float*)d_in[2];
    const float* sig = (const float*)d_in[3];
    int m = in_sizes[0] / D;   // 16384
    int n = in_sizes[1] / D;   // 8192

    k_bw1<<<BWB, 256>>>(tx);
    k_bw2<<<1, 32>>>(n);
    k_qprep<<<m / 256, 256>>>(x, m);
    k_tprep<<<n / 256, 256>>>(tx, tr, n);
    dim3 grid(m / MQ, TSPLIT);
    k_main_mma<<<grid, 256>>>(n);
    k_reduce<<<(m + 255) / 256, 256>>>(sig, m);
    k_final<<<(m + 255) / 256, 256>>>(sig, (float*)d_out, m);
}

// round 9
// speedup vs baseline: 2.4169x; 1.3545x over previous
#include <cuda_runtime.h>
#include <cuda_bf16.h>
#include <math.h>

#define D        32
#define TSPLIT   8
#define NTT      64            // train per tile
#define MQ       128           // queries per CTA
#define M_MAX    16384
#define N_MAX    8192
#define EPSV     1e-8f
#define BWB      64

// smem: pitch-80 rows. Tile buf: Bhi[0,5120) Blo[5120,10240) ext[10240,10752)
#define PITCH    80
#define BUFSZ    10752
#define SMEMSZ   (2*BUFSZ)

__device__ float         g_cl;
__device__ __nv_bfloat16 g_Ah[M_MAX * D];
__device__ __nv_bfloat16 g_Al[M_MAX * D];
__device__ __nv_bfloat16 g_Bh[N_MAX * D];
__device__ __nv_bfloat16 g_Bl[N_MAX * D];
__device__ float4        g_ext4[N_MAX / 2]; // {ct2_even, ct2_odd, r_even, r_odd}
__device__ float         g_qe[M_MAX];
__device__ double        g_bws [BWB * D];
__device__ double        g_bws2[BWB * D];
__device__ float         g_pnum[TSPLIT][M_MAX];
__device__ float         g_pden[TSPLIT][M_MAX];
__device__ float         g_rx[M_MAX];
__device__ unsigned int  g_rmin, g_rmax, g_smin, g_smax;

// ---------------- helpers ----------------
__device__ __forceinline__ unsigned long long pack2(float lo, float hi) {
    unsigned long long r; asm("mov.b64 %0, {%1, %2};" : "=l"(r) : "f"(lo), "f"(hi)); return r;
}
__device__ __forceinline__ unsigned long long dup2(float v) {
    unsigned long long r; asm("mov.b64 %0, {%1, %1};" : "=l"(r) : "f"(v)); return r;
}
__device__ __forceinline__ unsigned long long add2(unsigned long long a, unsigned long long b) {
    unsigned long long d; asm("add.rn.f32x2 %0, %1, %2;" : "=l"(d) : "l"(a), "l"(b)); return d;
}
__device__ __forceinline__ float2 unpack2(unsigned long long p) {
    float2 f; asm("mov.b64 {%0, %1}, %2;" : "=f"(f.x), "=f"(f.y) : "l"(p)); return f;
}
__device__ __forceinline__ float ex2f(float a) {
    float r; asm("ex2.approx.f32 %0, %1;" : "=f"(r) : "f"(a)); return r;
}
__device__ __forceinline__ void cp16(unsigned dst, const void* src) {
    asm volatile("cp.async.ca.shared.global [%0], [%1], 16;" :: "r"(dst), "l"(src));
}
__device__ __forceinline__ unsigned fenc(float f) {
    unsigned u = __float_as_uint(f); return (u & 0x80000000u) ? ~u : (u | 0x80000000u);
}
__device__ __forceinline__ float fdec(unsigned u) {
    u = (u & 0x80000000u) ? (u & 0x7fffffffu) : ~u; return __uint_as_float(u);
}
__device__ __forceinline__ float warp_min(float v) {
    #pragma unroll
    for (int o = 16; o; o >>= 1) v = fminf(v, __shfl_xor_sync(~0u, v, o));
    return v;
}
__device__ __forceinline__ float warp_max(float v) {
    #pragma unroll
    for (int o = 16; o; o >>= 1) v = fmaxf(v, __shfl_xor_sync(~0u, v, o));
    return v;
}
__device__ __forceinline__ void ldmx4(unsigned* r, unsigned addr) {
    asm volatile("ldmatrix.sync.aligned.m8n8.x4.shared.b16 {%0,%1,%2,%3}, [%4];"
                 : "=r"(r[0]), "=r"(r[1]), "=r"(r[2]), "=r"(r[3]) : "r"(addr));
}
__device__ __forceinline__ void mma16816(float* c, const unsigned* a, unsigned b0, unsigned b1) {
    asm volatile("mma.sync.aligned.m16n8k16.row.col.f32.bf16.bf16.f32 "
                 "{%0,%1,%2,%3}, {%4,%5,%6,%7}, {%8,%9}, {%0,%1,%2,%3};"
                 : "+f"(c[0]), "+f"(c[1]), "+f"(c[2]), "+f"(c[3])
                 : "r"(a[0]), "r"(a[1]), "r"(a[2]), "r"(a[3]), "r"(b0), "r"(b1));
}
__device__ __forceinline__ unsigned pbf2(float a, float b) {
    return (unsigned)__bfloat16_as_ushort(__float2bfloat16_rn(a)) |
           ((unsigned)__bfloat16_as_ushort(__float2bfloat16_rn(b)) << 16);
}

// ---------------- bandwidth ----------------
__global__ void k_bw1(const float* __restrict__ tx) {
    __shared__ double sds[8][8][4], sds2[8][8][4];
    const int tid = threadIdx.x, b = blockIdx.x;
    const float4* tx4 = (const float4*)tx;
    double s[4] = {0,0,0,0}, s2[4] = {0,0,0,0};
    #pragma unroll
    for (int it = 0; it < 4; it++) {
        float4 v = tx4[(size_t)(b * 128 + it * 32) * 8 + tid];
        double vx = v.x, vy = v.y, vz = v.z, vw = v.w;
        s[0] += vx; s2[0] += vx*vx; s[1] += vy; s2[1] += vy*vy;
        s[2] += vz; s2[2] += vz*vz; s[3] += vw; s2[3] += vw*vw;
    }
    #pragma unroll
    for (int o = 8; o <= 16; o <<= 1)
        #pragma unroll
        for (int k = 0; k < 4; k++) {
            s[k]  += __shfl_xor_sync(~0u, s[k],  o);
            s2[k] += __shfl_xor_sync(~0u, s2[k], o);
        }
    int w = tid >> 5, l = tid & 31;
    if (l < 8)
        #pragma unroll
        for (int k = 0; k < 4; k++) { sds[w][l][k] = s[k]; sds2[w][l][k] = s2[k]; }
    __syncthreads();
    if (tid < 8)
        #pragma unroll
        for (int k = 0; k < 4; k++) {
            double a = 0, a2 = 0;
            #pragma unroll
            for (int ww = 0; ww < 8; ww++) { a += sds[ww][tid][k]; a2 += sds2[ww][tid][k]; }
            g_bws[b * D + tid * 4 + k] = a; g_bws2[b * D + tid * 4 + k] = a2;
        }
}
__global__ void k_bw2(int n) {
    int d = threadIdx.x;
    double s = 0, s2 = 0;
    for (int b = 0; b < BWB; b++) { s += g_bws[b * D + d]; s2 += g_bws2[b * D + d]; }
    double mean = s / n, var = (s2 - n * mean * mean) / (n - 1);
    double sd = sqrt(var > 0.0 ? var : 0.0);
    #pragma unroll
    for (int o = 16; o; o >>= 1) sd += __shfl_xor_sync(~0u, sd, o);
    if (d == 0) {
        double bw = (sd / D) * exp(-log((double)n) / (D + 4));
        g_cl = (float)(1.0 / (2.0 * bw * bw) * 1.4426950408889634);
        g_rmin = ~0u; g_rmax = 0u; g_smin = ~0u; g_smax = 0u;
    }
}

// ---------------- coalesced prep: 8 threads per row ----------------
__global__ void k_qprep(const float* __restrict__ x, int m) {
    int idx = blockIdx.x * 256 + threadIdx.x;        // m*8 units
    int row = idx >> 3, g = idx & 7;
    float4 v = ((const float4*)x)[(size_t)row * 8 + g];
    float s = fmaf(v.x, v.x, fmaf(v.y, v.y, fmaf(v.z, v.z, v.w * v.w)));
    s += __shfl_xor_sync(~0u, s, 1);
    s += __shfl_xor_sync(~0u, s, 2);
    s += __shfl_xor_sync(~0u, s, 4);
    float cl = g_cl, K2 = cl + cl;
    float sx = v.x * K2, sy = v.y * K2, sz = v.z * K2, sw = v.w * K2;
    __nv_bfloat16 hx = __float2bfloat16_rn(sx), hy = __float2bfloat16_rn(sy);
    __nv_bfloat16 hz = __float2bfloat16_rn(sz), hw = __float2bfloat16_rn(sw);
    uint2 hi, lo;
    hi.x = (unsigned)__bfloat16_as_ushort(hx) | ((unsigned)__bfloat16_as_ushort(hy) << 16);
    hi.y = (unsigned)__bfloat16_as_ushort(hz) | ((unsigned)__bfloat16_as_ushort(hw) << 16);
    lo.x = pbf2(sx - __bfloat162float(hx), sy - __bfloat162float(hy));
    lo.y = pbf2(sz - __bfloat162float(hz), sw - __bfloat162float(hw));
    ((uint2*)g_Ah)[(size_t)row * 8 + g] = hi;
    ((uint2*)g_Al)[(size_t)row * 8 + g] = lo;
    if (g == 0) g_qe[row] = -cl * s;
}
__global__ void k_tprep(const float* __restrict__ tx, const float* __restrict__ tr, int n) {
    int idx = blockIdx.x * 256 + threadIdx.x;        // n*8 units
    int row = idx >> 3, g = idx & 7;
    float4 v = ((const float4*)tx)[(size_t)row * 8 + g];
    float s = fmaf(v.x, v.x, fmaf(v.y, v.y, fmaf(v.z, v.z, v.w * v.w)));
    s += __shfl_xor_sync(~0u, s, 1);
    s += __shfl_xor_sync(~0u, s, 2);
    s += __shfl_xor_sync(~0u, s, 4);
    __nv_bfloat16 hx = __float2bfloat16_rn(v.x), hy = __float2bfloat16_rn(v.y);
    __nv_bfloat16 hz = __float2bfloat16_rn(v.z), hw = __float2bfloat16_rn(v.w);
    uint2 hi, lo;
    hi.x = (unsigned)__bfloat16_as_ushort(hx) | ((unsigned)__bfloat16_as_ushort(hy) << 16);
    hi.y = (unsigned)__bfloat16_as_ushort(hz) | ((unsigned)__bfloat16_as_ushort(hw) << 16);
    lo.x = pbf2(v.x - __bfloat162float(hx), v.y - __bfloat162float(hy));
    lo.y = pbf2(v.z - __bfloat162float(hz), v.w - __bfloat162float(hw));
    ((uint2*)g_Bh)[(size_t)row * 8 + g] = hi;
    ((uint2*)g_Bl)[(size_t)row * 8 + g] = lo;
    if (g == 0) {
        float* e = (float*)&g_ext4[row >> 1];
        if (row & 1) { e[1] = -g_cl * s; e[3] = tr[row]; }
        else         { e[0] = -g_cl * s; e[2] = tr[row]; }
    }
}

// ---------------- HMMA KDE mainloop ----------------
__device__ __forceinline__ void load_tile(unsigned sb, int g, int b, int tid) {
    unsigned base = sb + b * BUFSZ;
    const __nv_bfloat16* sh = g_Bh + (size_t)g * NTT * D;
    const __nv_bfloat16* sl = g_Bl + (size_t)g * NTT * D;
    int row = tid >> 2, c = tid & 3;
    cp16(base + row * PITCH + c * 16, sh + row * D + c * 8);
    cp16(base + 5120 + row * PITCH + c * 16, sl + row * D + c * 8);
    if (tid < 32) cp16(base + 10240 + tid * 16, g_ext4 + (size_t)g * 32 + tid);
    asm volatile("cp.async.commit_group;" ::: "memory");
}

__global__ void __launch_bounds__(256, 3)
k_main_mma(int n) {
    __shared__ __align__(16) char smem[SMEMSZ];
    unsigned sb = (unsigned)__cvta_generic_to_shared(smem);
    const int tid = threadIdx.x, w = tid >> 5, lane = tid & 31;
    const int qblk = blockIdx.x, split = blockIdx.y;
    const int NT = (n / NTT) / TSPLIT;
    const int t0 = split * NT;

    // ---- stage A (hi at sb, lo at sb+10240), extract frags, reuse smem ----
    #pragma unroll
    for (int i = 0; i < 2; i++) {
        int idx = tid + i * 256, row = idx >> 2, c = idx & 3;
        cp16(sb + row * PITCH + c * 16, g_Ah + (size_t)(qblk * MQ + row) * D + c * 8);
        cp16(sb + 10240 + row * PITCH + c * 16, g_Al + (size_t)(qblk * MQ + row) * D + c * 8);
    }
    asm volatile("cp.async.commit_group;" ::: "memory");
    asm volatile("cp.async.wait_group 0;" ::: "memory");
    __syncthreads();

    unsigned ah[2][4], al[2][4];
    {
        unsigned rowsel = lane & 15, colb = (lane >> 4) * 16;
        unsigned abase = sb + (w * 16 + rowsel) * PITCH + colb;
        ldmx4(ah[0], abase);
        ldmx4(ah[1], abase + 32);
        ldmx4(al[0], abase + 10240);
        ldmx4(al[1], abase + 10240 + 32);
    }
    const int qg = lane >> 2;
    const unsigned long long cq2a = dup2(g_qe[qblk * MQ + w * 16 + qg]);
    const unsigned long long cq2b = dup2(g_qe[qblk * MQ + w * 16 + qg + 8]);
    __syncthreads();

    load_tile(sb, t0, 0, tid);

    float num_a = 0.f, den_a = 0.f, num_b = 0.f, den_b = 0.f;

    const unsigned browAdd = (lane >> 4) * 8 + (lane & 7);
    const unsigned bcolb   = ((lane >> 3) & 1) * 16;

    for (int i = 0; i < NT; i++) {
        const int buf = i & 1;
        if (i + 1 < NT) {
            load_tile(sb, t0 + i + 1, buf ^ 1, tid);
            asm volatile("cp.async.wait_group 1;" ::: "memory");
        } else {
            asm volatile("cp.async.wait_group 0;" ::: "memory");
        }
        __syncthreads();

        const unsigned bbase = sb + buf * BUFSZ;
        float c[8][4];
        #pragma unroll
        for (int s = 0; s < 8; s++)
            #pragma unroll
            for (int k = 0; k < 4; k++) c[s][k] = 0.f;

        #pragma unroll
        for (int np = 0; np < 4; np++) {
            const unsigned rb = bbase + (np * 16 + browAdd) * PITCH + bcolb;
            #pragma unroll
            for (int ks = 0; ks < 2; ks++) {
                unsigned bh[4], bl[4];
                ldmx4(bh, rb + ks * 32);
                ldmx4(bl, rb + 5120 + ks * 32);
                #pragma unroll
                for (int ns = 0; ns < 2; ns++) {
                    float* cc = c[np * 2 + ns];
                    mma16816(cc, ah[ks], bh[ns * 2], bh[ns * 2 + 1]);   // hh
                    mma16816(cc, al[ks], bh[ns * 2], bh[ns * 2 + 1]);   // lh
                    mma16816(cc, ah[ks], bl[ns * 2], bl[ns * 2 + 1]);   // hl
                    // ll dropped: |al·bl| ~ 2^-16 second-order, below tolerance
                }
            }
        }

        const float4* ext = (const float4*)(smem + buf * BUFSZ + 10240);
        #pragma unroll
        for (int s = 0; s < 8; s++) {
            float4 e = ext[s * 4 + (lane & 3)];
            unsigned long long ct = pack2(e.x, e.y);
            unsigned long long pa = add2(add2(pack2(c[s][0], c[s][1]), ct), cq2a);
            unsigned long long pb = add2(add2(pack2(c[s][2], c[s][3]), ct), cq2b);
            float2 fa = unpack2(pa), fb = unpack2(pb);
            float w0 = ex2f(fa.x), w1 = ex2f(fa.y);
            float w2 = ex2f(fb.x), w3 = ex2f(fb.y);
            num_a = fmaf(w0, e.z, num_a); num_a = fmaf(w1, e.w, num_a);
            den_a += w0 + w1;
            num_b = fmaf(w2, e.z, num_b); num_b = fmaf(w3, e.w, num_b);
            den_b += w2 + w3;
        }
        __syncthreads();
    }

    #pragma unroll
    for (int o = 1; o <= 2; o <<= 1) {
        num_a += __shfl_xor_sync(~0u, num_a, o);
        den_a += __shfl_xor_sync(~0u, den_a, o);
        num_b += __shfl_xor_sync(~0u, num_b, o);
        den_b += __shfl_xor_sync(~0u, den_b, o);
    }
    if ((lane & 3) == 0) {
        int q = qblk * MQ + w * 16 + qg;
        g_pnum[split][q] = num_a;     g_pden[split][q] = den_a;
        g_pnum[split][q + 8] = num_b; g_pden[split][q + 8] = den_b;
    }
}

// ---------------- reduce + final ----------------
__global__ void k_reduce(const float* __restrict__ sig, int m) {
    __shared__ float s_rmin[8], s_rmax[8], s_smin[8], s_smax[8];
    int q = blockIdx.x * blockDim.x + threadIdx.x;
    float rx = 3.4e38f, rxmx = -3.4e38f, sg = 3.4e38f, sgmx = -3.4e38f;
    if (q < m) {
        float num = 0.f, den = 0.f;
        #pragma unroll
        for (int s = 0; s < TSPLIT; s++) { num += g_pnum[s][q]; den += g_pden[s][q]; }
        float r = num / (den + EPSV);
        g_rx[q] = r; rx = r; rxmx = r;
        float sv = sig[q]; sg = sv; sgmx = sv;
    }
    float wr0 = warp_min(rx), wr1 = warp_max(rxmx), ws0 = warp_min(sg), ws1 = warp_max(sgmx);
    int w = threadIdx.x >> 5, l = threadIdx.x & 31, nw = blockDim.x >> 5;
    if (l == 0) { s_rmin[w] = wr0; s_rmax[w] = wr1; s_smin[w] = ws0; s_smax[w] = ws1; }
    __syncthreads();
    if (threadIdx.x == 0) {
        float a = s_rmin[0], b = s_rmax[0], cc = s_smin[0], d = s_smax[0];
        for (int i = 1; i < nw; i++) {
            a = fminf(a, s_rmin[i]); b = fmaxf(b, s_rmax[i]);
            cc = fminf(cc, s_smin[i]); d = fmaxf(d, s_smax[i]);
        }
        atomicMin(&g_rmin, fenc(a)); atomicMax(&g_rmax, fenc(b));
        atomicMin(&g_smin, fenc(cc)); atomicMax(&g_smax, fenc(d));
    }
}
__global__ void k_final(const float* __restrict__ sig, float* __restrict__ out, int m) {
    int q = blockIdx.x * blockDim.x + threadIdx.x;
    if (q >= m) return;
    float t1 = 0.5f * (g_rx[q] - fdec(g_rmin)) / (fdec(g_rmax) - fdec(g_rmin) + EPSV);
    float t2 = 0.5f * (sig[q]  - fdec(g_smin)) / (fdec(g_smax) - fdec(g_smin) + EPSV);
    out[q] = t1 + t2;
}

// ---------------- launch ----------------
extern "C" void kernel_launch(void* const* d_in, const int* in_sizes, int n_in,
                              void* d_out, int out_size) {
    const float* x   = (const float*)d_in[0];
    const float* tx  = (const float*)d_in[1];
    const float* tr  = (const float*)d_in[2];
    const float* sig = (const float*)d_in[3];
    int m = in_sizes[0] / D;   // 16384
    int n = in_sizes[1] / D;   // 8192

    k_bw1<<<BWB, 256>>>(tx);
    k_bw2<<<1, 32>>>(n);
    k_qprep<<<m * 8 / 256, 256>>>(x, m);
    k_tprep<<<n * 8 / 256, 256>>>(tx, tr, n);
    dim3 grid(m / MQ, TSPLIT);
    k_main_mma<<<grid, 256>>>(n);
    k_reduce<<<(m + 255) / 256, 256>>>(sig, m);
    k_final<<<(m + 255) / 256, 256>>>(sig, (float*)d_out, m);
}